// round 6
// baseline (speedup 1.0000x reference)
#include <cuda_runtime.h>

#define BATCH    1024
#define NS       64
#define BSTR     (BATCH * NS)       // float stride per timestep
#define SHIFT_C  4.5f

__device__ int g_perm[BATCH];       // rank (desc by length) -> batch index

// ---- packed f32x2 helpers (sm_103a) ----
__device__ __forceinline__ unsigned long long ffma2(unsigned long long a,
                                                    unsigned long long b,
                                                    unsigned long long c) {
    unsigned long long d;
    asm("fma.rn.f32x2 %0, %1, %2, %3;" : "=l"(d) : "l"(a), "l"(b), "l"(c));
    return d;
}
__device__ __forceinline__ unsigned long long fadd2(unsigned long long a,
                                                    unsigned long long b) {
    unsigned long long d;
    asm("add.rn.f32x2 %0, %1, %2;" : "=l"(d) : "l"(a), "l"(b));
    return d;
}
__device__ __forceinline__ unsigned long long pack2(float lo, float hi) {
    unsigned long long d;
    asm("mov.b64 %0, {%1, %2};" : "=l"(d)
        : "r"(__float_as_uint(lo)), "r"(__float_as_uint(hi)));
    return d;
}
__device__ __forceinline__ float lo32(unsigned long long v) {
    return __uint_as_float((unsigned)(v & 0xffffffffull));
}
__device__ __forceinline__ float hi32(unsigned long long v) {
    return __uint_as_float((unsigned)(v >> 32));
}

// ---- rank by length (descending), ties by index: perm is a bijection ----
__global__ void rank_kernel(const int* __restrict__ seq) {
    __shared__ int len[BATCH];
    const int tid = threadIdx.x;             // 128 threads
    for (int j = tid; j < BATCH; j += 128) len[j] = seq[j];
    __syncthreads();
    const int i  = blockIdx.x * 128 + tid;
    const int li = len[i];
    int r = 0;
#pragma unroll 8
    for (int j = 0; j < BATCH; j++) {
        int lj = len[j];
        r += (int)((lj > li) | ((lj == li) & (j < i)));
    }
    g_perm[r] = i;
}

// 8 warps/block: batch slot = warp/2 (4 batches/block), half = warp&1.
// Same-batch warps land on SMSPs (0,1) or (2,3). 2 blocks/SM.
__global__ void __launch_bounds__(256, 2)
crf_forward_kernel(const float* __restrict__ em,
                   const int*   __restrict__ seq,
                   const float* __restrict__ start,
                   const float* __restrict__ stop,
                   const float* __restrict__ trans,
                   float*       __restrict__ out)
{
    __shared__ __align__(16) float smem_alpha[2][4][NS];  // [parity][slot][state]
    __shared__ float zbuf[4];

    const int w    = threadIdx.x >> 5;
    const int lane = threadIdx.x & 31;
    const int slot = w >> 1;            // 0..3 batch slot in block
    const int half = w & 1;             // which 32 output states
    const int s    = 32 * half + lane;  // my output state

    // rank schedule: longs {2k,2k+1} paired with shorts {1023-2k,1022-2k}
    const int k2 = 2 * blockIdx.x;
    const int rank = (slot == 0) ? k2
                   : (slot == 1) ? k2 + 1
                   : (slot == 2) ? (BATCH - 1 - k2)
                                 : (BATCH - 2 - k2);
    const int b = g_perm[rank];

    // ---- one-time: E2[k] = exp(trans[s][2k..2k+1] - c), 32 f32x2 regs ----
    unsigned long long E2[32];
    {
        const float4* tr = (const float4*)(trans + s * NS);
#pragma unroll
        for (int j = 0; j < 16; j++) {
            float4 r = __ldg(tr + j);
            E2[2 * j]     = pack2(__expf(r.x - SHIFT_C), __expf(r.y - SHIFT_C));
            E2[2 * j + 1] = pack2(__expf(r.z - SHIFT_C), __expf(r.w - SHIFT_C));
        }
    }

    const int L   = seq[b];
    const int Lm1 = L - 1;
    const float* embase = em + b * NS + s;

    // ---- init: a = exp(start + em_0) ----
    float cur = __expf(__ldg(start + s) + __ldg(embase));
    float C = 0.0f;
    const float estop = __expf(__ldg(stop + s));
    smem_alpha[0][slot][s] = cur;
    asm volatile("bar.sync %0, %1;" :: "r"(slot + 1), "r"(64) : "memory");

    // ---- 8-deep RAW emission prefetch ring ----
    float ring[8];
#pragma unroll
    for (int i = 0; i < 8; i++) {
        int tt = (1 + i < Lm1) ? (1 + i) : Lm1;
        ring[i] = __ldg(embase + (size_t)tt * BSTR);
    }

    // One step: read smem_alpha[RD], write [WR], one named bar (64 thr).
    // RS_: rescale using previous alpha[0] (identical in both warps, no race).
#define CRF_BODY(eraw_, RD, WR, RS_)                                           \
    do {                                                                       \
        float eA = __expf(eraw_);                                              \
        const ulonglong2* a2 = (const ulonglong2*)(&smem_alpha[RD][slot][0]);  \
        unsigned long long acc0 = 0ull, acc1 = 0ull;                           \
        unsigned long long acc2 = 0ull, acc3 = 0ull;                           \
        _Pragma("unroll")                                                      \
        for (int j = 0; j < 16; j += 2) {                                      \
            ulonglong2 av0 = a2[j];                                            \
            ulonglong2 av1 = a2[j + 1];                                        \
            acc0 = ffma2(av0.x, E2[2 * j],     acc0);                          \
            acc1 = ffma2(av0.y, E2[2 * j + 1], acc1);                          \
            acc2 = ffma2(av1.x, E2[2 * j + 2], acc2);                          \
            acc3 = ffma2(av1.y, E2[2 * j + 3], acc3);                          \
        }                                                                      \
        unsigned long long va = fadd2(acc0, acc2);                             \
        unsigned long long vb = fadd2(acc1, acc3);                             \
        cur = ((lo32(va) + hi32(va)) + (lo32(vb) + hi32(vb))) * eA;            \
        if (RS_) {                                                             \
            float m = fmaxf(smem_alpha[RD][slot][0], 1e-30f);                  \
            cur *= __fdividef(1.0f, m);                                        \
            C += __logf(m);                                                    \
        }                                                                      \
        smem_alpha[WR][slot][s] = cur;                                         \
        asm volatile("bar.sync %0, %1;" :: "r"(slot + 1), "r"(64) : "memory"); \
    } while (0)

#define CRF_STEP(tcur_, ri_, RD, WR, RS_)                                      \
    do {                                                                       \
        float eraw = ring[ri_];                                                \
        int tp = (tcur_) + 8;                                                  \
        tp = (tp < Lm1) ? tp : Lm1;                                            \
        ring[ri_] = __ldg(embase + (size_t)tp * BSTR);                         \
        CRF_BODY(eraw, RD, WR, RS_);                                           \
    } while (0)

    int t = 1;
    for (; t + 7 < L; t += 8) {          // rescale every 8 steps (last of group)
        CRF_STEP(t,     0, 0, 1, false);
        CRF_STEP(t + 1, 1, 1, 0, false);
        CRF_STEP(t + 2, 2, 0, 1, false);
        CRF_STEP(t + 3, 3, 1, 0, false);
        CRF_STEP(t + 4, 4, 0, 1, false);
        CRF_STEP(t + 5, 5, 1, 0, false);
        CRF_STEP(t + 6, 6, 0, 1, false);
        CRF_STEP(t + 7, 7, 1, 0, true);
    }
    // tail: up to 7 steps (<=15 steps since last rescale: safe in fp32)
    if (t < L) { CRF_BODY(ring[0], 0, 1, false); t++; }
    if (t < L) { CRF_BODY(ring[1], 1, 0, false); t++; }
    if (t < L) { CRF_BODY(ring[2], 0, 1, false); t++; }
    if (t < L) { CRF_BODY(ring[3], 1, 0, false); t++; }
    if (t < L) { CRF_BODY(ring[4], 0, 1, false); t++; }
    if (t < L) { CRF_BODY(ring[5], 1, 0, false); t++; }
    if (t < L) { CRF_BODY(ring[6], 0, 1, false); }

    // ---- finalize: logZ = log(sum_s a[s]*exp(stop[s])) + C + c*(L-1) ----
    float z = cur * estop;
#pragma unroll
    for (int o = 16; o; o >>= 1)
        z += __shfl_xor_sync(0xffffffffu, z, o);
    if (half == 1 && lane == 0) zbuf[slot] = z;
    asm volatile("bar.sync %0, %1;" :: "r"(slot + 1), "r"(64) : "memory");
    if (half == 0 && lane == 0)
        out[b] = __logf(z + zbuf[slot]) + C + SHIFT_C * (float)(L - 1);
}

extern "C" void kernel_launch(void* const* d_in, const int* in_sizes, int n_in,
                              void* d_out, int out_size)
{
    const float* em    = (const float*)d_in[0];
    const int*   seq   = (const int*)d_in[1];
    const float* start = (const float*)d_in[2];
    const float* stop  = (const float*)d_in[3];
    const float* trans = (const float*)d_in[4];
    float*       out   = (float*)d_out;

    rank_kernel<<<BATCH / 128, 128>>>(seq);
    crf_forward_kernel<<<BATCH / 4, 256>>>(em, seq, start, stop, trans, out);
}

// round 7
// speedup vs baseline: 1.1170x; 1.1170x over previous
#include <cuda_runtime.h>
#include <cuda_bf16.h>

#define BATCH    1024
#define NS       64
#define F2_T     (BATCH * NS / 2)   // float2 stride per timestep
#define SHIFT_C  4.5f

__device__ int g_perm[BATCH];       // rank (desc by length) -> batch index

__device__ __forceinline__ __nv_bfloat162 u2b(unsigned u) {
    __nv_bfloat162 r;
    *reinterpret_cast<unsigned*>(&r) = u;
    return r;
}
__device__ __forceinline__ unsigned b2u(__nv_bfloat162 b) {
    return *reinterpret_cast<unsigned*>(&b);
}

// ---- rank by length (descending), ties by index: perm is a bijection ----
__global__ void rank_kernel(const int* __restrict__ seq) {
    __shared__ int len[BATCH];
    const int tid = threadIdx.x;             // 128 threads
    for (int j = tid; j < BATCH; j += 128) len[j] = seq[j];
    __syncthreads();
    const int i  = blockIdx.x * 128 + tid;
    const int li = len[i];
    int r = 0;
#pragma unroll 8
    for (int j = 0; j < BATCH; j++) {
        int lj = len[j];
        r += (int)((lj > li) | ((lj == li) & (j < i)));
    }
    g_perm[r] = i;
}

// 8 warps/block, grid 128: warp w and w+4 share SMSP w&3 (long + short batch).
__global__ void __launch_bounds__(256)
crf_forward_kernel(const float* __restrict__ em,
                   const int*   __restrict__ seq,
                   const float* __restrict__ start,
                   const float* __restrict__ stop,
                   const float* __restrict__ trans,
                   float*       __restrict__ out)
{
    const int w    = threadIdx.x >> 5;
    const int lane = threadIdx.x & 31;
    // long ranks on warps 0-3, complementary short ranks on warps 4-7
    const int rank = (w < 4) ? (4 * blockIdx.x + w)
                             : (BATCH - 1 - 4 * blockIdx.x - (w - 4));
    const int b    = g_perm[rank];

    // lane owns states s0 = 2*lane, s1 = 2*lane+1 (packed bf16x2: lo=s0, hi=s1)
    const int s0 = 2 * lane;

    // ---- one-time: E = bf16(exp(trans - c)); E0 row s0, E1 row s0+1 ----
    // E0[k] pairs inputs (2k, 2k+1): lo = E[s0][2k], hi = E[s0][2k+1]
    __nv_bfloat162 E0[32], E1[32];
    {
        const float4* tr0 = (const float4*)(trans + s0 * NS);
        const float4* tr1 = (const float4*)(trans + (s0 + 1) * NS);
#pragma unroll
        for (int j = 0; j < 16; j++) {
            float4 r0 = __ldg(tr0 + j);
            float4 r1 = __ldg(tr1 + j);
            E0[2 * j]     = __floats2bfloat162_rn(__expf(r0.x - SHIFT_C), __expf(r0.y - SHIFT_C));
            E0[2 * j + 1] = __floats2bfloat162_rn(__expf(r0.z - SHIFT_C), __expf(r0.w - SHIFT_C));
            E1[2 * j]     = __floats2bfloat162_rn(__expf(r1.x - SHIFT_C), __expf(r1.y - SHIFT_C));
            E1[2 * j + 1] = __floats2bfloat162_rn(__expf(r1.z - SHIFT_C), __expf(r1.w - SHIFT_C));
        }
    }

    const int L   = seq[b];
    const int Lm1 = L - 1;
    const float2* embase = (const float2*)em + (unsigned)b * (NS / 2) + lane;

    // ---- init: a = exp(start + em_0), fp32 + packed bf16 ----
    float2 st2 = ((const float2*)start)[lane];
    float2 em0 = __ldg(embase);
    float fx = __expf(st2.x + em0.x);
    float fy = __expf(st2.y + em0.y);
    unsigned curp = b2u(__floats2bfloat162_rn(fx, fy));
    float C = 0.0f;
    float2 sp2 = ((const float2*)stop)[lane];
    const float estop0 = __expf(sp2.x);
    const float estop1 = __expf(sp2.y);

    // ---- 8-deep RAW emission prefetch ring ----
    float2 ring[8];
#pragma unroll
    for (int i = 0; i < 8; i++) {
        int tt = (1 + i < Lm1) ? (1 + i) : Lm1;
        ring[i] = __ldg(embase + (unsigned)tt * F2_T);
    }

    const __nv_bfloat162 z2 = __floats2bfloat162_rn(0.0f, 0.0f);

    // One step: shfl-broadcast alpha, bf16 HFMA2 MACs, fp32 fold + emission.
#define CRF_BODY(eraw_)                                                        \
    do {                                                                       \
        float ex = __expf((eraw_).x);                                          \
        float ey = __expf((eraw_).y);                                          \
        __nv_bfloat162 a0 = z2, a1 = z2, a2 = z2, a3 = z2;                     \
        __nv_bfloat162 b0 = z2, b1 = z2, b2_ = z2, b3 = z2;                    \
        _Pragma("unroll")                                                      \
        for (int k = 0; k < 32; k += 4) {                                      \
            unsigned u0 = __shfl_sync(0xffffffffu, curp, k);                   \
            unsigned u1 = __shfl_sync(0xffffffffu, curp, k + 1);               \
            unsigned u2 = __shfl_sync(0xffffffffu, curp, k + 2);               \
            unsigned u3 = __shfl_sync(0xffffffffu, curp, k + 3);               \
            a0 = __hfma2(u2b(u0), E0[k],     a0);                              \
            b0 = __hfma2(u2b(u0), E1[k],     b0);                              \
            a1 = __hfma2(u2b(u1), E0[k + 1], a1);                              \
            b1 = __hfma2(u2b(u1), E1[k + 1], b1);                              \
            a2 = __hfma2(u2b(u2), E0[k + 2], a2);                              \
            b2_ = __hfma2(u2b(u2), E1[k + 2], b2_);                            \
            a3 = __hfma2(u2b(u3), E0[k + 3], a3);                              \
            b3 = __hfma2(u2b(u3), E1[k + 3], b3);                              \
        }                                                                      \
        __nv_bfloat162 A = __hadd2(__hadd2(a0, a1), __hadd2(a2, a3));          \
        __nv_bfloat162 B = __hadd2(__hadd2(b0, b1), __hadd2(b2_, b3));         \
        float vx = __low2float(A) + __high2float(A);                           \
        float vy = __low2float(B) + __high2float(B);                           \
        fx = vx * ex;                                                          \
        fy = vy * ey;                                                          \
        curp = b2u(__floats2bfloat162_rn(fx, fy));                             \
    } while (0)

#define CRF_STEP(tcur_, ri_)                                                   \
    do {                                                                       \
        float2 eraw = ring[ri_];                                               \
        int tp = (tcur_) + 8;                                                  \
        tp = (tp < Lm1) ? tp : Lm1;                                            \
        ring[ri_] = __ldg(embase + (unsigned)tp * F2_T);                       \
        CRF_BODY(eraw);                                                        \
    } while (0)

    int t = 1;
    for (; t + 7 < L; t += 8) {
        CRF_STEP(t,     0);
        CRF_STEP(t + 1, 1);
        CRF_STEP(t + 2, 2);
        CRF_STEP(t + 3, 3);
        CRF_STEP(t + 4, 4);
        CRF_STEP(t + 5, 5);
        CRF_STEP(t + 6, 6);
        CRF_STEP(t + 7, 7);
        // every 8 steps: exact rescale by state-0 alpha (uniform across lanes)
        float m = __shfl_sync(0xffffffffu, fx, 0);
        m = fmaxf(m, 1e-30f);
        float rv = __fdividef(1.0f, m);
        fx *= rv;
        fy *= rv;
        curp = b2u(__floats2bfloat162_rn(fx, fy));
        C += __logf(m);
    }
    // tail: up to 7 steps (fp32 range easily covers <16 unrescaled steps)
    if (t < L) { CRF_BODY(ring[0]); t++; }
    if (t < L) { CRF_BODY(ring[1]); t++; }
    if (t < L) { CRF_BODY(ring[2]); t++; }
    if (t < L) { CRF_BODY(ring[3]); t++; }
    if (t < L) { CRF_BODY(ring[4]); t++; }
    if (t < L) { CRF_BODY(ring[5]); t++; }
    if (t < L) { CRF_BODY(ring[6]); }

    // ---- finalize: logZ = log(sum_s a[s]*exp(stop[s])) + C + c*(L-1) ----
    float z = fx * estop0 + fy * estop1;
#pragma unroll
    for (int o = 16; o; o >>= 1)
        z += __shfl_xor_sync(0xffffffffu, z, o);
    if (lane == 0)
        out[b] = __logf(z) + C + SHIFT_C * (float)(L - 1);
}

extern "C" void kernel_launch(void* const* d_in, const int* in_sizes, int n_in,
                              void* d_out, int out_size)
{
    const float* em    = (const float*)d_in[0];
    const int*   seq   = (const int*)d_in[1];
    const float* start = (const float*)d_in[2];
    const float* stop  = (const float*)d_in[3];
    const float* trans = (const float*)d_in[4];
    float*       out   = (float*)d_out;

    rank_kernel<<<BATCH / 128, 128>>>(seq);
    crf_forward_kernel<<<BATCH / 8, 256>>>(em, seq, start, stop, trans, out);
}

// round 8
// speedup vs baseline: 1.6744x; 1.4990x over previous
#include <cuda_runtime.h>
#include <cuda_bf16.h>

#define BATCH    1024
#define NS       64
#define F2_T     (BATCH * NS / 2)   // float2 stride per timestep
#define SHIFT_C  4.5f

__device__ int g_perm[BATCH];       // rank (desc by length) -> batch index

__device__ __forceinline__ __nv_bfloat162 u2b(unsigned u) {
    __nv_bfloat162 r;
    *reinterpret_cast<unsigned*>(&r) = u;
    return r;
}
__device__ __forceinline__ unsigned b2u(__nv_bfloat162 b) {
    return *reinterpret_cast<unsigned*>(&b);
}

// ---- rank by length (descending), ties by index: perm is a bijection ----
__global__ void rank_kernel(const int* __restrict__ seq) {
    __shared__ int len[BATCH];
    const int tid = threadIdx.x;             // 128 threads
    for (int j = tid; j < BATCH; j += 128) len[j] = seq[j];
    __syncthreads();
    const int i  = blockIdx.x * 128 + tid;
    const int li = len[i];
    int r = 0;
#pragma unroll 8
    for (int j = 0; j < BATCH; j++) {
        int lj = len[j];
        r += (int)((lj > li) | ((lj == li) & (j < i)));
    }
    g_perm[r] = i;
}

// 16 warps/block (512 thr), 128 blocks = 1 wave.
// slot = w>>1 (8 batches/block), role = w&1 (0 = forward, 1 = backward).
__global__ void __launch_bounds__(512, 1)
crf_forward_kernel(const float* __restrict__ em,
                   const int*   __restrict__ seq,
                   const float* __restrict__ start,
                   const float* __restrict__ stop,
                   const float* __restrict__ trans,
                   float*       __restrict__ out)
{
    __shared__ float2 meet[8][32];   // fwd alpha at meeting point (f32)
    __shared__ float  cbuf[8];       // fwd log-scale accumulator

    const int w    = threadIdx.x >> 5;   // 0..15
    const int lane = threadIdx.x & 31;
    const int slot = w >> 1;             // 0..7
    const int role = w & 1;              // 0 fwd, 1 bwd
    const int k4   = 4 * blockIdx.x;
    const int rank = (slot < 4) ? (k4 + slot) : (BATCH - 1 - k4 - (slot - 4));
    const int b    = g_perm[rank];

    const int L  = seq[b];
    const int nf = L >> 1;           // forward MAC steps (consume e_1..e_nf)
    const int nb = L - 1 - nf;       // backward steps (consume e_{L-1}..e_{nf+1})
    const int s0 = 2 * lane;

    // ---- one-time E in bf16: fwd uses rows of trans, bwd uses columns ----
    __nv_bfloat162 E0[32], E1[32];
    if (role == 0) {
        const float4* tr0 = (const float4*)(trans + s0 * NS);
        const float4* tr1 = (const float4*)(trans + (s0 + 1) * NS);
#pragma unroll
        for (int j = 0; j < 16; j++) {
            float4 r0 = __ldg(tr0 + j);
            float4 r1 = __ldg(tr1 + j);
            E0[2 * j]     = __floats2bfloat162_rn(__expf(r0.x - SHIFT_C), __expf(r0.y - SHIFT_C));
            E0[2 * j + 1] = __floats2bfloat162_rn(__expf(r0.z - SHIFT_C), __expf(r0.w - SHIFT_C));
            E1[2 * j]     = __floats2bfloat162_rn(__expf(r1.x - SHIFT_C), __expf(r1.y - SHIFT_C));
            E1[2 * j + 1] = __floats2bfloat162_rn(__expf(r1.z - SHIFT_C), __expf(r1.w - SHIFT_C));
        }
    } else {
        // E0[k] = (Texp[2k][s0], Texp[2k+1][s0]); E1[k] same for column s0+1
#pragma unroll
        for (int k = 0; k < 32; k++) {
            float t00 = __ldg(trans + (2 * k)     * NS + s0);
            float t10 = __ldg(trans + (2 * k + 1) * NS + s0);
            float t01 = __ldg(trans + (2 * k)     * NS + s0 + 1);
            float t11 = __ldg(trans + (2 * k + 1) * NS + s0 + 1);
            E0[k] = __floats2bfloat162_rn(__expf(t00 - SHIFT_C), __expf(t10 - SHIFT_C));
            E1[k] = __floats2bfloat162_rn(__expf(t01 - SHIFT_C), __expf(t11 - SHIFT_C));
        }
    }

    const float2* embase = (const float2*)em + (unsigned)b * (NS / 2) + lane;
    const __nv_bfloat162 z2 = __floats2bfloat162_rn(0.0f, 0.0f);
    float C = 0.0f;

    // MAC core: exchange packed state via shfl, 64 HFMA2, fold to f32 (vx, vy)
#define MAC64(curp_, vx_, vy_)                                                 \
    do {                                                                       \
        __nv_bfloat162 a0 = z2, a1 = z2, b0 = z2, b1 = z2;                     \
        _Pragma("unroll")                                                      \
        for (int k = 0; k < 32; k += 2) {                                      \
            unsigned u0 = __shfl_sync(0xffffffffu, (curp_), k);                \
            unsigned u1 = __shfl_sync(0xffffffffu, (curp_), k + 1);            \
            a0 = __hfma2(u2b(u0), E0[k],     a0);                              \
            b0 = __hfma2(u2b(u0), E1[k],     b0);                              \
            a1 = __hfma2(u2b(u1), E0[k + 1], a1);                              \
            b1 = __hfma2(u2b(u1), E1[k + 1], b1);                              \
        }                                                                      \
        __nv_bfloat162 A = __hadd2(a0, a1);                                    \
        __nv_bfloat162 B = __hadd2(b0, b1);                                    \
        vx_ = __low2float(A) + __high2float(A);                                \
        vy_ = __low2float(B) + __high2float(B);                                \
    } while (0)

    float fx, fy;           // live state (alpha or beta) in f32
    unsigned curp;          // packed bf16x2 mirror

    if (role == 0) {
        // ================= FORWARD: alpha' = (T·alpha) ∘ e_t =================
        float2 st2 = ((const float2*)start)[lane];
        float2 em0 = __ldg(embase);
        fx = __expf(st2.x + em0.x);
        fy = __expf(st2.y + em0.y);
        curp = b2u(__floats2bfloat162_rn(fx, fy));

        float2 ring[8];
#pragma unroll
        for (int i = 0; i < 8; i++) {
            int tt = (1 + i < nf) ? (1 + i) : nf;
            tt = (tt > 0) ? tt : 0;
            ring[i] = __ldg(embase + (unsigned)tt * F2_T);
        }

#define FWD_BODY(eraw_)                                                        \
        do {                                                                   \
            float ex = __expf((eraw_).x);                                      \
            float ey = __expf((eraw_).y);                                      \
            float vx, vy;                                                      \
            MAC64(curp, vx, vy);                                               \
            fx = vx * ex;                                                      \
            fy = vy * ey;                                                      \
            curp = b2u(__floats2bfloat162_rn(fx, fy));                         \
        } while (0)

#define FWD_STEP(tcur_, ri_)                                                   \
        do {                                                                   \
            float2 eraw = ring[ri_];                                           \
            int tp = (tcur_) + 8;                                              \
            tp = (tp < nf) ? tp : nf;                                          \
            ring[ri_] = __ldg(embase + (unsigned)tp * F2_T);                   \
            FWD_BODY(eraw);                                                    \
        } while (0)

        int t = 1;
        for (; t + 7 <= nf; t += 8) {
            FWD_STEP(t,     0);
            FWD_STEP(t + 1, 1);
            FWD_STEP(t + 2, 2);
            FWD_STEP(t + 3, 3);
            FWD_STEP(t + 4, 4);
            FWD_STEP(t + 5, 5);
            FWD_STEP(t + 6, 6);
            FWD_STEP(t + 7, 7);
            float m = __shfl_sync(0xffffffffu, fx, 0);
            m = fmaxf(m, 1e-30f);
            float rv = __fdividef(1.0f, m);
            fx *= rv; fy *= rv;
            curp = b2u(__floats2bfloat162_rn(fx, fy));
            C += __logf(m);
        }
        if (t <= nf) { FWD_BODY(ring[0]); t++; }
        if (t <= nf) { FWD_BODY(ring[1]); t++; }
        if (t <= nf) { FWD_BODY(ring[2]); t++; }
        if (t <= nf) { FWD_BODY(ring[3]); t++; }
        if (t <= nf) { FWD_BODY(ring[4]); t++; }
        if (t <= nf) { FWD_BODY(ring[5]); t++; }
        if (t <= nf) { FWD_BODY(ring[6]); }

        // publish alpha_m + C_f, meet partner
        meet[slot][lane] = make_float2(fx, fy);
        if (lane == 0) cbuf[slot] = C;
        asm volatile("bar.sync %0, %1;" :: "r"(slot + 1), "r"(64) : "memory");
    } else {
        // ================ BACKWARD: beta' = Tᵀ·(beta ∘ e_t) =================
        float2 sp2 = ((const float2*)stop)[lane];
        fx = __expf(sp2.x);
        fy = __expf(sp2.y);

        float2 ring[8];
#pragma unroll
        for (int i = 0; i < 8; i++) {
            int tt = L - 1 - i;
            tt = (tt > 0) ? tt : 0;
            ring[i] = __ldg(embase + (unsigned)tt * F2_T);
        }

#define BWD_BODY(eraw_)                                                        \
        do {                                                                   \
            float gx = fx * __expf((eraw_).x);                                 \
            float gy = fy * __expf((eraw_).y);                                 \
            unsigned gp = b2u(__floats2bfloat162_rn(gx, gy));                  \
            MAC64(gp, fx, fy);                                                 \
        } while (0)

#define BWD_STEP(tcur_, ri_)                                                   \
        do {                                                                   \
            float2 eraw = ring[ri_];                                           \
            int tp = (tcur_) - 8;                                              \
            tp = (tp > 0) ? tp : 0;                                            \
            ring[ri_] = __ldg(embase + (unsigned)tp * F2_T);                   \
            BWD_BODY(eraw);                                                    \
        } while (0)

        int i = 0;
        int t = L - 1;
        for (; i + 7 < nb; i += 8, t -= 8) {
            BWD_STEP(t,     0);
            BWD_STEP(t - 1, 1);
            BWD_STEP(t - 2, 2);
            BWD_STEP(t - 3, 3);
            BWD_STEP(t - 4, 4);
            BWD_STEP(t - 5, 5);
            BWD_STEP(t - 6, 6);
            BWD_STEP(t - 7, 7);
            float m = __shfl_sync(0xffffffffu, fx, 0);
            m = fmaxf(m, 1e-30f);
            float rv = __fdividef(1.0f, m);
            fx *= rv; fy *= rv;
            C += __logf(m);
        }
        if (i < nb) { BWD_BODY(ring[0]); i++; }
        if (i < nb) { BWD_BODY(ring[1]); i++; }
        if (i < nb) { BWD_BODY(ring[2]); i++; }
        if (i < nb) { BWD_BODY(ring[3]); i++; }
        if (i < nb) { BWD_BODY(ring[4]); i++; }
        if (i < nb) { BWD_BODY(ring[5]); i++; }
        if (i < nb) { BWD_BODY(ring[6]); }

        asm volatile("bar.sync %0, %1;" :: "r"(slot + 1), "r"(64) : "memory");

        // combine: Z = sum_s alpha_m[s] * beta_m[s]
        float2 a = meet[slot][lane];
        float z = a.x * fx + a.y * fy;
#pragma unroll
        for (int o = 16; o; o >>= 1)
            z += __shfl_xor_sync(0xffffffffu, z, o);
        if (lane == 0)
            out[b] = __logf(z) + C + cbuf[slot] + SHIFT_C * (float)(L - 1);
    }
}

extern "C" void kernel_launch(void* const* d_in, const int* in_sizes, int n_in,
                              void* d_out, int out_size)
{
    const float* em    = (const float*)d_in[0];
    const int*   seq   = (const int*)d_in[1];
    const float* start = (const float*)d_in[2];
    const float* stop  = (const float*)d_in[3];
    const float* trans = (const float*)d_in[4];
    float*       out   = (float*)d_out;

    rank_kernel<<<BATCH / 128, 128>>>(seq);
    crf_forward_kernel<<<BATCH / 8, 512>>>(em, seq, start, stop, trans, out);
}

// round 9
// speedup vs baseline: 1.7597x; 1.0509x over previous
#include <cuda_runtime.h>
#include <cuda_bf16.h>

#define BATCH    1024
#define NS       64
#define F2_T     (BATCH * NS / 2)   // float2 stride per timestep
#define SHIFT_C  4.5f
#define NSLOT    7                  // batches per block
#define NWARP    (2 * NSLOT)        // 14 warps
#define NTHR     (32 * NWARP)       // 448 threads
#define NBLK     148                // one block per SM

__device__ int g_perm[BATCH];       // rank (desc by length) -> batch index

__device__ __forceinline__ __nv_bfloat162 u2b(unsigned u) {
    __nv_bfloat162 r;
    *reinterpret_cast<unsigned*>(&r) = u;
    return r;
}
__device__ __forceinline__ unsigned b2u(__nv_bfloat162 b) {
    return *reinterpret_cast<unsigned*>(&b);
}

// ---- rank by length (descending), ties by index: perm is a bijection ----
__global__ void rank_kernel(const int* __restrict__ seq) {
    __shared__ int len[BATCH];
    const int tid = threadIdx.x;             // 128 threads
    for (int j = tid; j < BATCH; j += 128) len[j] = seq[j];
    __syncthreads();
    const int i  = blockIdx.x * 128 + tid;
    const int li = len[i];
    int r = 0;
#pragma unroll 8
    for (int j = 0; j < BATCH; j++) {
        int lj = len[j];
        r += (int)((lj > li) | ((lj == li) & (j < i)));
    }
    g_perm[r] = i;
}

// 14 warps/block, grid 148 (all SMs). slot = w>>1, role = w&1 (0 fwd, 1 bwd).
// Stripe schedule (ranks split into 7 stripes of 148):
//   slots {0,2,4,6} (SMSP 0,1) -> stripes {1,2,4,6}, snake-paired: ~const sum
//   slots {1,3,5}   (SMSP 2,3) -> stripes {0,3,5}: lighter group
__global__ void __launch_bounds__(NTHR, 1)
crf_forward_kernel(const float* __restrict__ em,
                   const int*   __restrict__ seq,
                   const float* __restrict__ start,
                   const float* __restrict__ stop,
                   const float* __restrict__ trans,
                   float*       __restrict__ out)
{
    __shared__ unsigned xbuf[NWARP][2][32];  // per-warp exchange, dbl-buffered
    __shared__ float2   meet[NSLOT][32];     // fwd alpha at meeting point
    __shared__ float    cbuf[NSLOT];         // fwd log-scale accumulator

    const int w    = threadIdx.x >> 5;       // 0..13
    const int lane = threadIdx.x & 31;
    const int slot = w >> 1;                 // 0..6
    const int role = w & 1;                  // 0 fwd, 1 bwd
    const int blk  = blockIdx.x;             // 0..147

    // slot -> stripe, direction
    const int stripe = (slot == 0) ? 1 : (slot == 1) ? 0 : slot;
    const int dir    = (slot == 2) | (slot == 3) | (slot == 6);
    const int idx    = dir ? (147 - blk) : blk;
    const int rank   = stripe * 148 + idx;
    if (rank >= BATCH) return;               // dummy slot (both warps agree)
    const int b = g_perm[rank];

    const int L  = seq[b];
    const int nf = L >> 1;                   // forward steps (e_1..e_nf)
    const int nb = L - 1 - nf;               // backward steps (e_{L-1}..e_{nf+1})
    const int s0 = 2 * lane;

    // ---- one-time E in bf16: fwd uses rows of trans, bwd uses columns ----
    __nv_bfloat162 E0[32], E1[32];
    if (role == 0) {
        const float4* tr0 = (const float4*)(trans + s0 * NS);
        const float4* tr1 = (const float4*)(trans + (s0 + 1) * NS);
#pragma unroll
        for (int j = 0; j < 16; j++) {
            float4 r0 = __ldg(tr0 + j);
            float4 r1 = __ldg(tr1 + j);
            E0[2 * j]     = __floats2bfloat162_rn(__expf(r0.x - SHIFT_C), __expf(r0.y - SHIFT_C));
            E0[2 * j + 1] = __floats2bfloat162_rn(__expf(r0.z - SHIFT_C), __expf(r0.w - SHIFT_C));
            E1[2 * j]     = __floats2bfloat162_rn(__expf(r1.x - SHIFT_C), __expf(r1.y - SHIFT_C));
            E1[2 * j + 1] = __floats2bfloat162_rn(__expf(r1.z - SHIFT_C), __expf(r1.w - SHIFT_C));
        }
    } else {
#pragma unroll
        for (int k = 0; k < 32; k++) {
            float t00 = __ldg(trans + (2 * k)     * NS + s0);
            float t10 = __ldg(trans + (2 * k + 1) * NS + s0);
            float t01 = __ldg(trans + (2 * k)     * NS + s0 + 1);
            float t11 = __ldg(trans + (2 * k + 1) * NS + s0 + 1);
            E0[k] = __floats2bfloat162_rn(__expf(t00 - SHIFT_C), __expf(t10 - SHIFT_C));
            E1[k] = __floats2bfloat162_rn(__expf(t01 - SHIFT_C), __expf(t11 - SHIFT_C));
        }
    }

    const float2* embase = (const float2*)em + (unsigned)b * (NS / 2) + lane;
    const __nv_bfloat162 z2 = __floats2bfloat162_rn(0.0f, 0.0f);
    float C = 0.0f;
    float fx, fy;            // live state (alpha or beta) in f32
    unsigned curp;           // packed bf16x2 mirror

    // MAC core via per-warp smem broadcast (dbl-buffer P_, one syncwarp).
#define MACX(P_, inpk_, vx_, vy_)                                              \
    do {                                                                       \
        xbuf[w][P_][lane] = (inpk_);                                           \
        __syncwarp();                                                          \
        const uint4* xb = (const uint4*)xbuf[w][P_];                           \
        __nv_bfloat162 a0 = z2, a1 = z2, b0 = z2, b1 = z2;                     \
        _Pragma("unroll")                                                      \
        for (int j = 0; j < 8; j++) {                                          \
            uint4 q = xb[j];                                                   \
            a0 = __hfma2(u2b(q.x), E0[4 * j],     a0);                         \
            b0 = __hfma2(u2b(q.x), E1[4 * j],     b0);                         \
            a1 = __hfma2(u2b(q.y), E0[4 * j + 1], a1);                         \
            b1 = __hfma2(u2b(q.y), E1[4 * j + 1], b1);                         \
            a0 = __hfma2(u2b(q.z), E0[4 * j + 2], a0);                         \
            b0 = __hfma2(u2b(q.z), E1[4 * j + 2], b0);                         \
            a1 = __hfma2(u2b(q.w), E0[4 * j + 3], a1);                         \
            b1 = __hfma2(u2b(q.w), E1[4 * j + 3], b1);                         \
        }                                                                      \
        __nv_bfloat162 A = __hadd2(a0, a1);                                    \
        __nv_bfloat162 B = __hadd2(b0, b1);                                    \
        vx_ = __low2float(A) + __high2float(A);                                \
        vy_ = __low2float(B) + __high2float(B);                                \
    } while (0)

    if (role == 0) {
        // ================= FORWARD: alpha' = (T·alpha) ∘ e_t =================
        float2 st2 = ((const float2*)start)[lane];
        float2 em0 = __ldg(embase);
        fx = __expf(st2.x + em0.x);
        fy = __expf(st2.y + em0.y);
        curp = b2u(__floats2bfloat162_rn(fx, fy));

        float2 ring[8];
#pragma unroll
        for (int i = 0; i < 8; i++) {
            int tt = (1 + i < nf) ? (1 + i) : nf;
            ring[i] = __ldg(embase + (unsigned)tt * F2_T);
        }

#define FWD_BODY(eraw_, P_)                                                    \
        do {                                                                   \
            float ex = __expf((eraw_).x);                                      \
            float ey = __expf((eraw_).y);                                      \
            float vx, vy;                                                      \
            MACX(P_, curp, vx, vy);                                            \
            fx = vx * ex;                                                      \
            fy = vy * ey;                                                      \
            curp = b2u(__floats2bfloat162_rn(fx, fy));                         \
        } while (0)

#define FWD_STEP(tcur_, ri_, P_)                                               \
        do {                                                                   \
            float2 eraw = ring[ri_];                                           \
            int tp = (tcur_) + 8;                                              \
            tp = (tp < nf) ? tp : nf;                                          \
            ring[ri_] = __ldg(embase + (unsigned)tp * F2_T);                   \
            FWD_BODY(eraw, P_);                                                \
        } while (0)

        int t = 1;
        for (; t + 7 <= nf; t += 8) {
            FWD_STEP(t,     0, 0);
            FWD_STEP(t + 1, 1, 1);
            FWD_STEP(t + 2, 2, 0);
            FWD_STEP(t + 3, 3, 1);
            FWD_STEP(t + 4, 4, 0);
            FWD_STEP(t + 5, 5, 1);
            FWD_STEP(t + 6, 6, 0);
            FWD_STEP(t + 7, 7, 1);
            float m = __shfl_sync(0xffffffffu, fx, 0);
            m = fmaxf(m, 1e-30f);
            float rv = __fdividef(1.0f, m);
            fx *= rv; fy *= rv;
            curp = b2u(__floats2bfloat162_rn(fx, fy));
            C += __logf(m);
        }
        if (t <= nf) { FWD_BODY(ring[0], 0); t++; }
        if (t <= nf) { FWD_BODY(ring[1], 1); t++; }
        if (t <= nf) { FWD_BODY(ring[2], 0); t++; }
        if (t <= nf) { FWD_BODY(ring[3], 1); t++; }
        if (t <= nf) { FWD_BODY(ring[4], 0); t++; }
        if (t <= nf) { FWD_BODY(ring[5], 1); t++; }
        if (t <= nf) { FWD_BODY(ring[6], 0); }

        meet[slot][lane] = make_float2(fx, fy);
        if (lane == 0) cbuf[slot] = C;
        asm volatile("bar.sync %0, %1;" :: "r"(slot + 1), "r"(64) : "memory");
    } else {
        // ================ BACKWARD: beta' = Tᵀ·(beta ∘ e_t) =================
        float2 sp2 = ((const float2*)stop)[lane];
        fx = __expf(sp2.x);
        fy = __expf(sp2.y);

        float2 ring[8];
#pragma unroll
        for (int i = 0; i < 8; i++) {
            int tt = L - 1 - i;
            tt = (tt > 0) ? tt : 0;
            ring[i] = __ldg(embase + (unsigned)tt * F2_T);
        }

#define BWD_BODY(eraw_, P_)                                                    \
        do {                                                                   \
            float gx = fx * __expf((eraw_).x);                                 \
            float gy = fy * __expf((eraw_).y);                                 \
            unsigned gp = b2u(__floats2bfloat162_rn(gx, gy));                  \
            MACX(P_, gp, fx, fy);                                              \
        } while (0)

#define BWD_STEP(tcur_, ri_, P_)                                               \
        do {                                                                   \
            float2 eraw = ring[ri_];                                           \
            int tp = (tcur_) - 8;                                              \
            tp = (tp > 0) ? tp : 0;                                            \
            ring[ri_] = __ldg(embase + (unsigned)tp * F2_T);                   \
            BWD_BODY(eraw, P_);                                                \
        } while (0)

        int i = 0;
        int t = L - 1;
        for (; i + 7 < nb; i += 8, t -= 8) {
            BWD_STEP(t,     0, 0);
            BWD_STEP(t - 1, 1, 1);
            BWD_STEP(t - 2, 2, 0);
            BWD_STEP(t - 3, 3, 1);
            BWD_STEP(t - 4, 4, 0);
            BWD_STEP(t - 5, 5, 1);
            BWD_STEP(t - 6, 6, 0);
            BWD_STEP(t - 7, 7, 1);
            float m = __shfl_sync(0xffffffffu, fx, 0);
            m = fmaxf(m, 1e-30f);
            float rv = __fdividef(1.0f, m);
            fx *= rv; fy *= rv;
            C += __logf(m);
        }
        if (i < nb) { BWD_BODY(ring[0], 0); i++; }
        if (i < nb) { BWD_BODY(ring[1], 1); i++; }
        if (i < nb) { BWD_BODY(ring[2], 0); i++; }
        if (i < nb) { BWD_BODY(ring[3], 1); i++; }
        if (i < nb) { BWD_BODY(ring[4], 0); i++; }
        if (i < nb) { BWD_BODY(ring[5], 1); i++; }
        if (i < nb) { BWD_BODY(ring[6], 0); }

        asm volatile("bar.sync %0, %1;" :: "r"(slot + 1), "r"(64) : "memory");

        // combine: Z = sum_s alpha_m[s] * beta_m[s]
        float2 a = meet[slot][lane];
        float z = a.x * fx + a.y * fy;
#pragma unroll
        for (int o = 16; o; o >>= 1)
            z += __shfl_xor_sync(0xffffffffu, z, o);
        if (lane == 0)
            out[b] = __logf(z) + C + cbuf[slot] + SHIFT_C * (float)(L - 1);
    }
}

extern "C" void kernel_launch(void* const* d_in, const int* in_sizes, int n_in,
                              void* d_out, int out_size)
{
    const float* em    = (const float*)d_in[0];
    const int*   seq   = (const int*)d_in[1];
    const float* start = (const float*)d_in[2];
    const float* stop  = (const float*)d_in[3];
    const float* trans = (const float*)d_in[4];
    float*       out   = (float*)d_out;

    rank_kernel<<<BATCH / 128, 128>>>(seq);
    crf_forward_kernel<<<NBLK, NTHR>>>(em, seq, start, stop, trans, out);
}